// round 14
// baseline (speedup 1.0000x reference)
#include <cuda_runtime.h>
#include <cuda_bf16.h>
#include <cstdint>

#define NROWS 8192
#define DCOLS 512

// ---------------- scratch (device globals: allocation-free) ----------------
__device__ __align__(256) int8_t g_A1[(size_t)NROWS * NROWS];   // 64 MB
__device__ __align__(256) int8_t g_A2[(size_t)NROWS * NROWS];   // 64 MB
__device__ __align__(256) int8_t g_B1[(size_t)DCOLS * NROWS];   // 4 MB [n][k]
__device__ __align__(256) int8_t g_B2[(size_t)DCOLS * NROWS];   // 4 MB
__device__ __align__(256) int   g_part[(size_t)NROWS * DCOLS];  // 16 MB (a1*b1)
__device__ float g_deg[NROWS];
__device__ float g_Sa[NROWS];
__device__ float g_Sb[DCOLS];

// ---------------- PTX helpers (compute_100-safe: no 'a' features) ----------
__device__ __forceinline__ uint32_t smem_u32(const void* p) {
    uint32_t a;
    asm("{ .reg .u64 t; cvta.to.shared.u64 t, %1; cvt.u32.u64 %0, t; }" : "=r"(a) : "l"(p));
    return a;
}
__device__ __forceinline__ void cp16(uint32_t dst, const void* src) {
    asm volatile("cp.async.cg.shared.global [%0], [%1], 16;" :: "r"(dst), "l"(src));
}
__device__ __forceinline__ void ldsm4(uint32_t* r, uint32_t addr) {
    asm volatile("ldmatrix.sync.aligned.m8n8.x4.shared.b16 {%0,%1,%2,%3}, [%4];"
                 : "=r"(r[0]), "=r"(r[1]), "=r"(r[2]), "=r"(r[3]) : "r"(addr));
}
__device__ __forceinline__ void mma_s8(int* c, const uint32_t* a, const uint32_t* b) {
    asm("mma.sync.aligned.m16n8k32.row.col.s32.s8.s8.s32 "
        "{%0,%1,%2,%3}, {%4,%5,%6,%7}, {%8,%9}, {%0,%1,%2,%3};"
        : "+r"(c[0]), "+r"(c[1]), "+r"(c[2]), "+r"(c[3])
        : "r"(a[0]), "r"(a[1]), "r"(a[2]), "r"(a[3]), "r"(b[0]), "r"(b[1]));
}

// ---------------- P1: row stats + XLA-order deg + int8 quant ----------------
// Single streaming pass: load row as float2 in XLA thread order into registers,
// count positives + max/min in the same pass; apply a' transform ONCE in regs;
// deg (XLA order) and quantization both read the transformed registers.
__global__ void __launch_bounds__(256) prep_rows(const float* __restrict__ inc) {
    __shared__ int   red_c[8];
    __shared__ float red_mp[8];
    __shared__ float red_mn[8];
    __shared__ float wpart[32];
    __shared__ float s_hv, s_inv;

    const int r = blockIdx.x;
    const int tid = threadIdx.x;
    const int lane = tid & 31, warp = tid >> 5;
    const float2* src = (const float2*)(inc + (size_t)r * NROWS);

    // load 16 float2 in XLA order: pair p = tid + 256*jv + 1024*i
    float vx[16], vy[16];
    int cnt = 0;
    float mp = 0.f;     // max value (>=0; >0 iff a positive exists)
    float mn = 0.f;     // min value (<=0)
    #pragma unroll
    for (int jv = 0; jv < 4; jv++) {
        #pragma unroll
        for (int i = 0; i < 4; i++) {
            const int p = tid + 256 * jv + 1024 * i;
            float2 v = src[p];
            vx[jv * 4 + i] = v.x;
            vy[jv * 4 + i] = v.y;
            cnt += (v.x > 0.f) + (v.y > 0.f);
            mp = fmaxf(mp, fmaxf(v.x, v.y));
            mn = fminf(mn, fminf(v.x, v.y));
        }
    }
    for (int o = 16; o; o >>= 1) {
        cnt += __shfl_xor_sync(0xFFFFFFFFu, cnt, o);
        mp = fmaxf(mp, __shfl_xor_sync(0xFFFFFFFFu, mp, o));
        mn = fminf(mn, __shfl_xor_sync(0xFFFFFFFFu, mn, o));
    }
    if (lane == 0) { red_c[warp] = cnt; red_mp[warp] = mp; red_mn[warp] = mn; }
    __syncthreads();
    if (tid == 0) {
        int c = 0;
        float MP = 0.f, MN = 0.f;
        #pragma unroll
        for (int i = 0; i < 8; i++) {
            c += red_c[i];
            MP = fmaxf(MP, red_mp[i]);
            MN = fminf(MN, red_mn[i]);
        }
        float denom = __fsqrt_rn((float)c);
        denom = fmaxf(denom, 1e-12f);
        float hv = __fdiv_rn(1.0f, denom);
        s_hv = hv;
        // max|a'| = max(fl(maxpos+hv), -minneg); exact (fp add monotone)
        float m = fmaxf((MP > 0.f) ? (MP + hv) : 0.f, -MN);
        m = fmaxf(m, 1e-30f);
        g_Sa[r] = m / 127.f;
        s_inv = 127.f / m;
    }
    __syncthreads();
    const float hv = s_hv;
    const float inv = s_inv;

    // transform ONCE in registers: a' = (x>0) ? x+hv : x
    #pragma unroll
    for (int e = 0; e < 16; e++) {
        if (vx[e] > 0.f) vx[e] = vx[e] + hv;
        if (vy[e] > 0.f) vy[e] = vy[e] + hv;
    }

    // deg: XLA-GPU row-reduce order mimic, from transformed registers
    #pragma unroll
    for (int jv = 0; jv < 4; jv++) {
        float ax = 0.f, ay = 0.f;
        #pragma unroll
        for (int i = 0; i < 4; i++) {
            ax += vx[jv * 4 + i];
            ay += vy[jv * 4 + i];
        }
        float s = ax + ay;
        s += __shfl_down_sync(0xFFFFFFFFu, s, 16);
        s += __shfl_down_sync(0xFFFFFFFFu, s, 8);
        s += __shfl_down_sync(0xFFFFFFFFu, s, 4);
        s += __shfl_down_sync(0xFFFFFFFFu, s, 2);
        s += __shfl_down_sync(0xFFFFFFFFu, s, 1);
        if (lane == 0) wpart[jv * 8 + warp] = s;
    }
    __syncthreads();
    if (tid < 32) {
        float v = wpart[tid];
        v += __shfl_down_sync(0xFFFFFFFFu, v, 16);
        v += __shfl_down_sync(0xFFFFFFFFu, v, 8);
        v += __shfl_down_sync(0xFFFFFFFFu, v, 4);
        v += __shfl_down_sync(0xFFFFFFFFu, v, 2);
        v += __shfl_down_sync(0xFFFFFFFFu, v, 1);
        if (tid == 0) g_deg[r] = v;
    }

    // quantize from transformed registers: a' = Sa*(q1 + q2/254)
    int8_t* A1 = g_A1 + (size_t)r * NROWS;
    int8_t* A2 = g_A2 + (size_t)r * NROWS;
    #pragma unroll
    for (int jv = 0; jv < 4; jv++) {
        #pragma unroll
        for (int i = 0; i < 4; i++) {
            const int j = 2 * tid + 512 * jv + 2048 * i;
            float qx = vx[jv * 4 + i] * inv;
            float qy = vy[jv * 4 + i] * inv;
            int i1x = __float2int_rn(qx);
            int i1y = __float2int_rn(qy);
            int i2x = __float2int_rn(254.f * (qx - (float)i1x));
            int i2y = __float2int_rn(254.f * (qy - (float)i1y));
            *(char2*)(A1 + j) = make_char2((char)i1x, (char)i1y);
            *(char2*)(A2 + j) = make_char2((char)i2x, (char)i2y);
        }
    }
}

// ---------------- P2a: per-column max of cur -> g_Sb ----------------
__global__ void __launch_bounds__(256) prep_Bscale(const float* __restrict__ cur) {
    __shared__ float red[32][8];
    const int tid = threadIdx.x;
    const int nIn = tid & 7;
    const int kp = tid >> 3;
    const int n = blockIdx.x * 8 + nIn;
    float m = 0.f;
    for (int k = kp; k < NROWS; k += 32)
        m = fmaxf(m, fabsf(cur[(size_t)k * DCOLS + n]));
    red[kp][nIn] = m;
    __syncthreads();
    if (tid < 8) {
        float mm = 1e-30f;
        #pragma unroll
        for (int i = 0; i < 32; i++) mm = fmaxf(mm, red[i][tid]);
        g_Sb[blockIdx.x * 8 + tid] = mm / 127.f;
    }
}

// ---------------- P2b: cur [k][n] -> int8 planes [n][k] ----------------
__global__ void __launch_bounds__(256) prep_B(const float* __restrict__ cur) {
    __shared__ float t[32][33];
    const int k0 = blockIdx.x * 32;
    const int n0 = blockIdx.y * 32;
    const int tx = threadIdx.x, ty = threadIdx.y;
    for (int i = ty; i < 32; i += 8)
        t[i][tx] = cur[(size_t)(k0 + i) * DCOLS + n0 + tx];
    __syncthreads();
    for (int i = ty; i < 32; i += 8) {
        const int n = n0 + i;
        float v = t[tx][i];
        float q = v / g_Sb[n];
        int i1 = __float2int_rn(q);
        int i2 = __float2int_rn(254.f * (q - (float)i1));
        size_t o = (size_t)n * NROWS + (size_t)(k0 + tx);
        g_B1[o] = (int8_t)i1;
        g_B2[o] = (int8_t)i2;
    }
}

// ---------------- P3: fused int8 x3 GEMM -------------------------------------
// CTA tile 128x128, 256 threads, warp grid 4(m) x 2(n), warp tile 32x64.
// Phase 1: part = a1*b1 (BK=128, 2 planes) -> g_part (own tile, L2 round trip).
// Phase 2: ax = a2*b1 + a1*b2 (BK=64, 4 planes); epilogue reads own g_part tile.
constexpr int BM = 128, BN = 128;
constexpr int BK1 = 128, NCH1 = NROWS / BK1;            // 64 chunks
constexpr int TILE1 = BM * BK1;                          // 16 KB per operand
constexpr int STAGE1 = 2 * TILE1;                        // 32 KB
constexpr int BK2 = 64, NCH2 = NROWS / BK2;             // 128 chunks
constexpr int A_BYTES2 = BM * 128;                       // 16 KB ([q1 64B | q2 64B])
constexpr int B_BYTES2 = BN * 128;                       // 16 KB
constexpr int STAGE2 = A_BYTES2 + B_BYTES2;              // 32 KB
constexpr int SMEM_G = 1024 + 3 * STAGE1;                // 99328 (STAGE1==STAGE2)

__device__ __forceinline__ void load_stage1(uint32_t st, int c, int m0, int n0, int tid) {
    const size_t rs = (size_t)NROWS;
    const size_t kb = (size_t)c * BK1;
    const char* A1 = (const char*)g_A1 + (size_t)m0 * rs + kb;
    const char* B1 = (const char*)g_B1 + (size_t)n0 * rs + kb;
    #pragma unroll
    for (int i = 0; i < 4; i++) {
        int idx = i * 256 + tid, row = idx >> 3, g = idx & 7;
        cp16(st + row * 128 + ((g ^ (row & 7)) << 4), A1 + (size_t)row * rs + (size_t)g * 16);
    }
    const uint32_t bs = st + TILE1;
    #pragma unroll
    for (int i = 0; i < 4; i++) {
        int idx = i * 256 + tid, row = idx >> 3, g = idx & 7;
        cp16(bs + row * 128 + ((g ^ (row & 7)) << 4), B1 + (size_t)row * rs + (size_t)g * 16);
    }
}

__device__ __forceinline__ void load_stage2(uint32_t st, int c, int m0, int n0, int tid) {
    const size_t rs = (size_t)NROWS;
    const size_t kb = (size_t)c * BK2;
    const char* A1 = (const char*)g_A1 + (size_t)m0 * rs + kb;
    const char* A2 = (const char*)g_A2 + (size_t)m0 * rs + kb;
    const char* B1 = (const char*)g_B1 + (size_t)n0 * rs + kb;
    const char* B2 = (const char*)g_B2 + (size_t)n0 * rs + kb;
    #pragma unroll
    for (int i = 0; i < 4; i++) {
        int idx = i * 256 + tid, row = idx >> 3, g = idx & 7;
        const char* s = (g < 4 ? A1 : A2) + (size_t)row * rs + (size_t)(g & 3) * 16;
        cp16(st + row * 128 + ((g ^ (row & 7)) << 4), s);
    }
    const uint32_t bs = st + A_BYTES2;
    #pragma unroll
    for (int i = 0; i < 4; i++) {
        int idx = i * 256 + tid, row = idx >> 3, g = idx & 7;
        const char* s = (g < 4 ? B1 : B2) + (size_t)row * rs + (size_t)(g & 3) * 16;
        cp16(bs + row * 128 + ((g ^ (row & 7)) << 4), s);
    }
}

__global__ void __launch_bounds__(256, 2) gemm_fused(float* __restrict__ out) {
    extern __shared__ char smem_raw[];
    const uint32_t sb = (smem_u32(smem_raw) + 1023u) & ~1023u;
    const int tid = threadIdx.x, lane = tid & 31, w = tid >> 5;
    const int wm = w & 3, wn = w >> 2;
    const int m0 = blockIdx.y * BM, n0 = blockIdx.x * BN;
    const uint32_t stage0 = sb + 1024;

    int aRow[2], bRow[4];
    #pragma unroll
    for (int mi = 0; mi < 2; mi++) aRow[mi] = wm * 32 + mi * 16 + (lane & 15);
    #pragma unroll
    for (int f = 0; f < 4; f++)
        bRow[f] = wn * 64 + f * 16 + ((lane >> 4) << 3) + (lane & 7);
    const int aSel = lane >> 4;
    const int bSel = (lane >> 3) & 1;
    const int cw = n0 + wn * 64 + (lane & 3) * 2;

    // ================= Phase 1: main (a1*b1) =================
    #pragma unroll
    for (int s = 0; s < 2; s++) {
        load_stage1(stage0 + s * STAGE1, s, m0, n0, tid);
        asm volatile("cp.async.commit_group;" ::: "memory");
    }
    {
        int am[2][8][4] = {};
        for (int c = 0; c < NCH1; c++) {
            asm volatile("cp.async.wait_group 1;" ::: "memory");
            __syncthreads();
            if (c + 2 < NCH1) load_stage1(stage0 + ((c + 2) % 3) * STAGE1, c + 2, m0, n0, tid);
            asm volatile("cp.async.commit_group;" ::: "memory");

            const uint32_t st = stage0 + (c % 3) * STAGE1;
            const uint32_t aB = st, bB = st + TILE1;
            #pragma unroll
            for (int s = 0; s < 4; s++) {
                uint32_t ah[8], bb[8];
                #pragma unroll
                for (int mi = 0; mi < 2; mi++)
                    ldsm4(&ah[4 * mi], aB + aRow[mi] * 128 +
                          (((2 * s + aSel) ^ (aRow[mi] & 7)) << 4));
                #pragma unroll
                for (int h = 0; h < 2; h++) {
                    #pragma unroll
                    for (int g = 0; g < 2; g++) {
                        const int f = 2 * h + g;
                        ldsm4(&bb[4 * g], bB + bRow[f] * 128 +
                              (((2 * s + bSel) ^ (bRow[f] & 7)) << 4));
                    }
                    #pragma unroll
                    for (int mi = 0; mi < 2; mi++)
                        #pragma unroll
                        for (int j = 0; j < 4; j++)
                            mma_s8(am[mi][4 * h + j], &ah[4 * mi], &bb[2 * j]);
                }
            }
        }
        // stash partials (own tile; re-read by SAME thread in phase-2 epilogue)
        #pragma unroll
        for (int mi = 0; mi < 2; mi++) {
            const int r0 = m0 + wm * 32 + mi * 16 + (lane >> 2);
            int* p0 = g_part + (size_t)r0 * DCOLS;
            int* p1 = g_part + (size_t)(r0 + 8) * DCOLS;
            #pragma unroll
            for (int ni = 0; ni < 8; ni++) {
                *(int2*)(p0 + cw + ni * 8) = make_int2(am[mi][ni][0], am[mi][ni][1]);
                *(int2*)(p1 + cw + ni * 8) = make_int2(am[mi][ni][2], am[mi][ni][3]);
            }
        }
    }
    // all warps done with phase-1 buffers before reuse
    asm volatile("cp.async.wait_group 0;" ::: "memory");
    __syncthreads();

    // ================= Phase 2: cross (a2*b1 + a1*b2) =================
    #pragma unroll
    for (int s = 0; s < 2; s++) {
        load_stage2(stage0 + s * STAGE2, s, m0, n0, tid);
        asm volatile("cp.async.commit_group;" ::: "memory");
    }
    int ax[2][8][4] = {};
    for (int c = 0; c < NCH2; c++) {
        asm volatile("cp.async.wait_group 1;" ::: "memory");
        __syncthreads();
        if (c + 2 < NCH2) load_stage2(stage0 + ((c + 2) % 3) * STAGE2, c + 2, m0, n0, tid);
        asm volatile("cp.async.commit_group;" ::: "memory");

        const uint32_t st = stage0 + (c % 3) * STAGE2;
        const uint32_t aB = st, bB = st + A_BYTES2;
        #pragma unroll
        for (int q = 0; q < 2; q++) {
            uint32_t ah[8], al[8], bb[8];
            #pragma unroll
            for (int mi = 0; mi < 2; mi++) {
                ldsm4(&ah[4 * mi], aB + aRow[mi] * 128 +
                      (((q * 2 + aSel) ^ (aRow[mi] & 7)) << 4));     // plane q1
                ldsm4(&al[4 * mi], aB + aRow[mi] * 128 +
                      (((4 + q * 2 + aSel) ^ (aRow[mi] & 7)) << 4)); // plane q2
            }
            #pragma unroll
            for (int h = 0; h < 2; h++) {
                #pragma unroll
                for (int g = 0; g < 2; g++) {        // b1
                    const int f = 2 * h + g;
                    ldsm4(&bb[4 * g], bB + bRow[f] * 128 +
                          (((q * 2 + bSel) ^ (bRow[f] & 7)) << 4));
                }
                #pragma unroll
                for (int mi = 0; mi < 2; mi++)
                    #pragma unroll
                    for (int j = 0; j < 4; j++)
                        mma_s8(ax[mi][4 * h + j], &al[4 * mi], &bb[2 * j]);  // a2*b1
                #pragma unroll
                for (int g = 0; g < 2; g++) {        // b2 overwrites
                    const int f = 2 * h + g;
                    ldsm4(&bb[4 * g], bB + bRow[f] * 128 +
                          (((4 + q * 2 + bSel) ^ (bRow[f] & 7)) << 4));
                }
                #pragma unroll
                for (int mi = 0; mi < 2; mi++)
                    #pragma unroll
                    for (int j = 0; j < 4; j++)
                        mma_s8(ax[mi][4 * h + j], &ah[4 * mi], &bb[2 * j]);  // a1*b2
            }
        }
    }

    // epilogue: fea = Sa*Sb*(part + ax/254); out = fea / deg (RN)
    const float C = 1.f / 254.f;
    #pragma unroll
    for (int mi = 0; mi < 2; mi++) {
        const int r0 = m0 + wm * 32 + mi * 16 + (lane >> 2);
        const float d0 = g_deg[r0], d1 = g_deg[r0 + 8];
        const float sa0 = g_Sa[r0], sa1 = g_Sa[r0 + 8];
        const int* q0 = g_part + (size_t)r0 * DCOLS;
        const int* q1 = g_part + (size_t)(r0 + 8) * DCOLS;
        float* p0 = out + (size_t)r0 * DCOLS;
        float* p1 = out + (size_t)(r0 + 8) * DCOLS;
        #pragma unroll
        for (int ni = 0; ni < 8; ni++) {
            const int col = cw + ni * 8;
            float2 sbv = *(const float2*)(g_Sb + col);
            int2 m0v = *(const int2*)(q0 + col);
            int2 m1v = *(const int2*)(q1 + col);
            float f00 = sa0 * sbv.x * ((float)m0v.x + (float)ax[mi][ni][0] * C);
            float f01 = sa0 * sbv.y * ((float)m0v.y + (float)ax[mi][ni][1] * C);
            float f10 = sa1 * sbv.x * ((float)m1v.x + (float)ax[mi][ni][2] * C);
            float f11 = sa1 * sbv.y * ((float)m1v.y + (float)ax[mi][ni][3] * C);
            *(float2*)(p0 + col) = make_float2(__fdiv_rn(f00, d0), __fdiv_rn(f01, d0));
            *(float2*)(p1 + col) = make_float2(__fdiv_rn(f10, d1), __fdiv_rn(f11, d1));
        }
    }
}

// ---------------- launch ----------------
extern "C" void kernel_launch(void* const* d_in, const int* in_sizes, int n_in,
                              void* d_out, int out_size) {
    const float* cur = (const float*)d_in[0];
    const float* inc = (const float*)d_in[1];
    if (n_in >= 2 && in_sizes[0] == NROWS * NROWS) {  // defensive input-order check
        inc = (const float*)d_in[0];
        cur = (const float*)d_in[1];
    }
    cudaFuncSetAttribute(gemm_fused, cudaFuncAttributeMaxDynamicSharedMemorySize, SMEM_G);

    prep_rows<<<NROWS, 256>>>(inc);
    prep_Bscale<<<DCOLS / 8, 256>>>(cur);
    prep_B<<<dim3(NROWS / 32, DCOLS / 32), dim3(32, 8)>>>(cur);
    gemm_fused<<<dim3(DCOLS / BN, NROWS / BM), 256, SMEM_G>>>((float*)d_out);
}

// round 15
// speedup vs baseline: 1.0495x; 1.0495x over previous
#include <cuda_runtime.h>
#include <cuda_bf16.h>
#include <cstdint>

#define NROWS 8192
#define DCOLS 512

// ---------------- scratch (device globals: allocation-free) ----------------
__device__ __align__(256) int8_t g_A1[(size_t)NROWS * NROWS];   // 64 MB
__device__ __align__(256) int8_t g_A2[(size_t)NROWS * NROWS];   // 64 MB
__device__ __align__(256) int8_t g_B1[(size_t)DCOLS * NROWS];   // 4 MB [n][k]
__device__ __align__(256) int8_t g_B2[(size_t)DCOLS * NROWS];   // 4 MB
__device__ __align__(256) int   g_part[(size_t)NROWS * DCOLS];  // 16 MB (a1*b1)
__device__ __align__(256) int   g_part2[(size_t)NROWS * DCOLS]; // 16 MB (a2*b1)
__device__ float g_deg[NROWS];
__device__ float g_Sa[NROWS];
__device__ float g_Sb[DCOLS];

// ---------------- PTX helpers (compute_100-safe: no 'a' features) ----------
__device__ __forceinline__ uint32_t smem_u32(const void* p) {
    uint32_t a;
    asm("{ .reg .u64 t; cvta.to.shared.u64 t, %1; cvt.u32.u64 %0, t; }" : "=r"(a) : "l"(p));
    return a;
}
__device__ __forceinline__ void cp16(uint32_t dst, const void* src) {
    asm volatile("cp.async.cg.shared.global [%0], [%1], 16;" :: "r"(dst), "l"(src));
}
__device__ __forceinline__ void ldsm4(uint32_t* r, uint32_t addr) {
    asm volatile("ldmatrix.sync.aligned.m8n8.x4.shared.b16 {%0,%1,%2,%3}, [%4];"
                 : "=r"(r[0]), "=r"(r[1]), "=r"(r[2]), "=r"(r[3]) : "r"(addr));
}
__device__ __forceinline__ void mma_s8(int* c, const uint32_t* a, const uint32_t* b) {
    asm("mma.sync.aligned.m16n8k32.row.col.s32.s8.s8.s32 "
        "{%0,%1,%2,%3}, {%4,%5,%6,%7}, {%8,%9}, {%0,%1,%2,%3};"
        : "+r"(c[0]), "+r"(c[1]), "+r"(c[2]), "+r"(c[3])
        : "r"(a[0]), "r"(a[1]), "r"(a[2]), "r"(a[3]), "r"(b[0]), "r"(b[1]));
}

// ---------------- P1: row stats + XLA-order deg + int8 quant ----------------
__global__ void __launch_bounds__(256) prep_rows(const float* __restrict__ inc) {
    __shared__ int   red_c[8];
    __shared__ float red_mp[8];
    __shared__ float red_mn[8];
    __shared__ float wpart[32];
    __shared__ float s_hv, s_inv;

    const int r = blockIdx.x;
    const int tid = threadIdx.x;
    const int lane = tid & 31, warp = tid >> 5;
    const float2* src = (const float2*)(inc + (size_t)r * NROWS);

    // load 16 float2 in XLA order: pair p = tid + 256*jv + 1024*i
    float vx[16], vy[16];
    int cnt = 0;
    float mp = 0.f, mn = 0.f;
    #pragma unroll
    for (int jv = 0; jv < 4; jv++) {
        #pragma unroll
        for (int i = 0; i < 4; i++) {
            const int p = tid + 256 * jv + 1024 * i;
            float2 v = src[p];
            vx[jv * 4 + i] = v.x;
            vy[jv * 4 + i] = v.y;
            cnt += (v.x > 0.f) + (v.y > 0.f);
            mp = fmaxf(mp, fmaxf(v.x, v.y));
            mn = fminf(mn, fminf(v.x, v.y));
        }
    }
    for (int o = 16; o; o >>= 1) {
        cnt += __shfl_xor_sync(0xFFFFFFFFu, cnt, o);
        mp = fmaxf(mp, __shfl_xor_sync(0xFFFFFFFFu, mp, o));
        mn = fminf(mn, __shfl_xor_sync(0xFFFFFFFFu, mn, o));
    }
    if (lane == 0) { red_c[warp] = cnt; red_mp[warp] = mp; red_mn[warp] = mn; }
    __syncthreads();
    if (tid == 0) {
        int c = 0;
        float MP = 0.f, MN = 0.f;
        #pragma unroll
        for (int i = 0; i < 8; i++) {
            c += red_c[i];
            MP = fmaxf(MP, red_mp[i]);
            MN = fminf(MN, red_mn[i]);
        }
        float denom = __fsqrt_rn((float)c);
        denom = fmaxf(denom, 1e-12f);
        float hv = __fdiv_rn(1.0f, denom);
        s_hv = hv;
        float m = fmaxf((MP > 0.f) ? (MP + hv) : 0.f, -MN);
        m = fmaxf(m, 1e-30f);
        g_Sa[r] = m / 127.f;
        s_inv = 127.f / m;
    }
    __syncthreads();
    const float hv = s_hv;
    const float inv = s_inv;

    // transform ONCE in registers: a' = (x>0) ? x+hv : x
    #pragma unroll
    for (int e = 0; e < 16; e++) {
        if (vx[e] > 0.f) vx[e] = vx[e] + hv;
        if (vy[e] > 0.f) vy[e] = vy[e] + hv;
    }

    // deg: XLA-GPU row-reduce order mimic
    #pragma unroll
    for (int jv = 0; jv < 4; jv++) {
        float ax = 0.f, ay = 0.f;
        #pragma unroll
        for (int i = 0; i < 4; i++) {
            ax += vx[jv * 4 + i];
            ay += vy[jv * 4 + i];
        }
        float s = ax + ay;
        s += __shfl_down_sync(0xFFFFFFFFu, s, 16);
        s += __shfl_down_sync(0xFFFFFFFFu, s, 8);
        s += __shfl_down_sync(0xFFFFFFFFu, s, 4);
        s += __shfl_down_sync(0xFFFFFFFFu, s, 2);
        s += __shfl_down_sync(0xFFFFFFFFu, s, 1);
        if (lane == 0) wpart[jv * 8 + warp] = s;
    }
    __syncthreads();
    if (tid < 32) {
        float v = wpart[tid];
        v += __shfl_down_sync(0xFFFFFFFFu, v, 16);
        v += __shfl_down_sync(0xFFFFFFFFu, v, 8);
        v += __shfl_down_sync(0xFFFFFFFFu, v, 4);
        v += __shfl_down_sync(0xFFFFFFFFu, v, 2);
        v += __shfl_down_sync(0xFFFFFFFFu, v, 1);
        if (tid == 0) g_deg[r] = v;
    }

    // quantize: a' = Sa*(q1 + q2/254)
    int8_t* A1 = g_A1 + (size_t)r * NROWS;
    int8_t* A2 = g_A2 + (size_t)r * NROWS;
    #pragma unroll
    for (int jv = 0; jv < 4; jv++) {
        #pragma unroll
        for (int i = 0; i < 4; i++) {
            const int j = 2 * tid + 512 * jv + 2048 * i;
            float qx = vx[jv * 4 + i] * inv;
            float qy = vy[jv * 4 + i] * inv;
            int i1x = __float2int_rn(qx);
            int i1y = __float2int_rn(qy);
            int i2x = __float2int_rn(254.f * (qx - (float)i1x));
            int i2y = __float2int_rn(254.f * (qy - (float)i1y));
            *(char2*)(A1 + j) = make_char2((char)i1x, (char)i1y);
            *(char2*)(A2 + j) = make_char2((char)i2x, (char)i2y);
        }
    }
}

// ---------------- P2a: per-column max of cur -> g_Sb ----------------
__global__ void __launch_bounds__(256) prep_Bscale(const float* __restrict__ cur) {
    __shared__ float red[32][8];
    const int tid = threadIdx.x;
    const int nIn = tid & 7;
    const int kp = tid >> 3;
    const int n = blockIdx.x * 8 + nIn;
    float m = 0.f;
    for (int k = kp; k < NROWS; k += 32)
        m = fmaxf(m, fabsf(cur[(size_t)k * DCOLS + n]));
    red[kp][nIn] = m;
    __syncthreads();
    if (tid < 8) {
        float mm = 1e-30f;
        #pragma unroll
        for (int i = 0; i < 32; i++) mm = fmaxf(mm, red[i][tid]);
        g_Sb[blockIdx.x * 8 + tid] = mm / 127.f;
    }
}

// ---------------- P2b: cur [k][n] -> int8 planes [n][k] ----------------
__global__ void __launch_bounds__(256) prep_B(const float* __restrict__ cur) {
    __shared__ float t[32][33];
    const int k0 = blockIdx.x * 32;
    const int n0 = blockIdx.y * 32;
    const int tx = threadIdx.x, ty = threadIdx.y;
    for (int i = ty; i < 32; i += 8)
        t[i][tx] = cur[(size_t)(k0 + i) * DCOLS + n0 + tx];
    __syncthreads();
    for (int i = ty; i < 32; i += 8) {
        const int n = n0 + i;
        float v = t[tx][i];
        float q = v / g_Sb[n];
        int i1 = __float2int_rn(q);
        int i2 = __float2int_rn(254.f * (q - (float)i1));
        size_t o = (size_t)n * NROWS + (size_t)(k0 + tx);
        g_B1[o] = (int8_t)i1;
        g_B2[o] = (int8_t)i2;
    }
}

// ---------------- GEMM: 3 identical BK128 2-plane passes ---------------------
// CTA tile 128x128, 256 threads, warp grid 4(m) x 2(n), warp tile 32x64.
// grid 4x64 = 256 CTAs, occ 2 -> one fully-resident wave per pass.
constexpr int BM = 128, BN = 128;
constexpr int BK = 128, NCH = NROWS / BK;               // 64 chunks
constexpr int TILE = BM * BK;                            // 16 KB per operand
constexpr int STAGE = 2 * TILE;                          // 32 KB
constexpr int SMEM_G = 1024 + 3 * STAGE;                 // 99328

__device__ __forceinline__ void load_stageP(uint32_t st, int c, int m0, int n0, int tid,
                                            const int8_t* Ap, const int8_t* Bp) {
    const size_t rs = (size_t)NROWS;
    const size_t kb = (size_t)c * BK;
    const char* A = (const char*)Ap + (size_t)m0 * rs + kb;
    const char* B = (const char*)Bp + (size_t)n0 * rs + kb;
    #pragma unroll
    for (int i = 0; i < 4; i++) {
        int idx = i * 256 + tid, row = idx >> 3, g = idx & 7;
        cp16(st + row * 128 + ((g ^ (row & 7)) << 4), A + (size_t)row * rs + (size_t)g * 16);
    }
    const uint32_t bs = st + TILE;
    #pragma unroll
    for (int i = 0; i < 4; i++) {
        int idx = i * 256 + tid, row = idx >> 3, g = idx & 7;
        cp16(bs + row * 128 + ((g ^ (row & 7)) << 4), B + (size_t)row * rs + (size_t)g * 16);
    }
}

// Shared mainloop: accumulates Ap x Bp^T tile into am.
__device__ __forceinline__ void gemm_loop(int am[2][8][4], const int8_t* Ap,
                                          const int8_t* Bp, uint32_t stage0,
                                          int m0, int n0, int tid,
                                          const int* aRow, const int* bRow,
                                          int aSel, int bSel) {
    #pragma unroll
    for (int s = 0; s < 2; s++) {
        load_stageP(stage0 + s * STAGE, s, m0, n0, tid, Ap, Bp);
        asm volatile("cp.async.commit_group;" ::: "memory");
    }
    for (int c = 0; c < NCH; c++) {
        asm volatile("cp.async.wait_group 1;" ::: "memory");
        __syncthreads();
        if (c + 2 < NCH) load_stageP(stage0 + ((c + 2) % 3) * STAGE, c + 2, m0, n0, tid, Ap, Bp);
        asm volatile("cp.async.commit_group;" ::: "memory");

        const uint32_t st = stage0 + (c % 3) * STAGE;
        const uint32_t aB = st, bB = st + TILE;
        #pragma unroll
        for (int s = 0; s < 4; s++) {        // four k32 steps
            uint32_t ah[8], bb[8];
            #pragma unroll
            for (int mi = 0; mi < 2; mi++)
                ldsm4(&ah[4 * mi], aB + aRow[mi] * 128 +
                      (((2 * s + aSel) ^ (aRow[mi] & 7)) << 4));
            #pragma unroll
            for (int h = 0; h < 2; h++) {
                #pragma unroll
                for (int g = 0; g < 2; g++) {
                    const int f = 2 * h + g;
                    ldsm4(&bb[4 * g], bB + bRow[f] * 128 +
                          (((2 * s + bSel) ^ (bRow[f] & 7)) << 4));
                }
                #pragma unroll
                for (int mi = 0; mi < 2; mi++)
                    #pragma unroll
                    for (int j = 0; j < 4; j++)
                        mma_s8(am[mi][4 * h + j], &ah[4 * mi], &bb[2 * j]);
            }
        }
    }
}

// passes 1 & 2: write int32 partial tile (sel=0: A1*B1 -> g_part; sel=1: A2*B1 -> g_part2)
__global__ void __launch_bounds__(256, 2) gemm_term(int sel) {
    extern __shared__ char smem_raw[];
    const uint32_t sb = (smem_u32(smem_raw) + 1023u) & ~1023u;
    const int tid = threadIdx.x, lane = tid & 31, w = tid >> 5;
    const int wm = w & 3, wn = w >> 2;
    const int m0 = blockIdx.y * BM, n0 = blockIdx.x * BN;

    const int8_t* Ap = sel ? g_A2 : g_A1;
    int* partOut = sel ? g_part2 : g_part;

    int aRow[2], bRow[4];
    #pragma unroll
    for (int mi = 0; mi < 2; mi++) aRow[mi] = wm * 32 + mi * 16 + (lane & 15);
    #pragma unroll
    for (int f = 0; f < 4; f++)
        bRow[f] = wn * 64 + f * 16 + ((lane >> 4) << 3) + (lane & 7);
    const int aSel = lane >> 4;
    const int bSel = (lane >> 3) & 1;

    int am[2][8][4] = {};
    gemm_loop(am, Ap, g_B1, sb + 1024, m0, n0, tid, aRow, bRow, aSel, bSel);

    const int cw = n0 + wn * 64 + (lane & 3) * 2;
    #pragma unroll
    for (int mi = 0; mi < 2; mi++) {
        const int r0 = m0 + wm * 32 + mi * 16 + (lane >> 2);
        int* p0 = partOut + (size_t)r0 * DCOLS;
        int* p1 = partOut + (size_t)(r0 + 8) * DCOLS;
        #pragma unroll
        for (int ni = 0; ni < 8; ni++) {
            *(int2*)(p0 + cw + ni * 8) = make_int2(am[mi][ni][0], am[mi][ni][1]);
            *(int2*)(p1 + cw + ni * 8) = make_int2(am[mi][ni][2], am[mi][ni][3]);
        }
    }
}

// pass 3: A1*B2; epilogue: fea = Sa*Sb*(part + (part2 + acc)/254); out = fea/deg
__global__ void __launch_bounds__(256, 2) gemm_final(float* __restrict__ out) {
    extern __shared__ char smem_raw[];
    const uint32_t sb = (smem_u32(smem_raw) + 1023u) & ~1023u;
    const int tid = threadIdx.x, lane = tid & 31, w = tid >> 5;
    const int wm = w & 3, wn = w >> 2;
    const int m0 = blockIdx.y * BM, n0 = blockIdx.x * BN;

    int aRow[2], bRow[4];
    #pragma unroll
    for (int mi = 0; mi < 2; mi++) aRow[mi] = wm * 32 + mi * 16 + (lane & 15);
    #pragma unroll
    for (int f = 0; f < 4; f++)
        bRow[f] = wn * 64 + f * 16 + ((lane >> 4) << 3) + (lane & 7);
    const int aSel = lane >> 4;
    const int bSel = (lane >> 3) & 1;

    int am[2][8][4] = {};
    gemm_loop(am, g_A1, g_B2, sb + 1024, m0, n0, tid, aRow, bRow, aSel, bSel);

    const float C = 1.f / 254.f;
    const int cw = n0 + wn * 64 + (lane & 3) * 2;
    #pragma unroll
    for (int mi = 0; mi < 2; mi++) {
        const int r0 = m0 + wm * 32 + mi * 16 + (lane >> 2);
        const float d0 = g_deg[r0], d1 = g_deg[r0 + 8];
        const float sa0 = g_Sa[r0], sa1 = g_Sa[r0 + 8];
        const int* q0 = g_part + (size_t)r0 * DCOLS;
        const int* q1 = g_part + (size_t)(r0 + 8) * DCOLS;
        const int* x0 = g_part2 + (size_t)r0 * DCOLS;
        const int* x1 = g_part2 + (size_t)(r0 + 8) * DCOLS;
        float* p0 = out + (size_t)r0 * DCOLS;
        float* p1 = out + (size_t)(r0 + 8) * DCOLS;
        #pragma unroll
        for (int ni = 0; ni < 8; ni++) {
            const int col = cw + ni * 8;
            float2 sbv = *(const float2*)(g_Sb + col);
            int2 m0v = *(const int2*)(q0 + col);
            int2 m1v = *(const int2*)(q1 + col);
            int2 c0v = *(const int2*)(x0 + col);
            int2 c1v = *(const int2*)(x1 + col);
            float f00 = sa0 * sbv.x * ((float)m0v.x + (float)(c0v.x + am[mi][ni][0]) * C);
            float f01 = sa0 * sbv.y * ((float)m0v.y + (float)(c0v.y + am[mi][ni][1]) * C);
            float f10 = sa1 * sbv.x * ((float)m1v.x + (float)(c1v.x + am[mi][ni][2]) * C);
            float f11 = sa1 * sbv.y * ((float)m1v.y + (float)(c1v.y + am[mi][ni][3]) * C);
            *(float2*)(p0 + col) = make_float2(__fdiv_rn(f00, d0), __fdiv_rn(f01, d0));
            *(float2*)(p1 + col) = make_float2(__fdiv_rn(f10, d1), __fdiv_rn(f11, d1));
        }
    }
}

// ---------------- launch ----------------
extern "C" void kernel_launch(void* const* d_in, const int* in_sizes, int n_in,
                              void* d_out, int out_size) {
    const float* cur = (const float*)d_in[0];
    const float* inc = (const float*)d_in[1];
    if (n_in >= 2 && in_sizes[0] == NROWS * NROWS) {  // defensive input-order check
        inc = (const float*)d_in[0];
        cur = (const float*)d_in[1];
    }
    cudaFuncSetAttribute(gemm_term, cudaFuncAttributeMaxDynamicSharedMemorySize, SMEM_G);
    cudaFuncSetAttribute(gemm_final, cudaFuncAttributeMaxDynamicSharedMemorySize, SMEM_G);

    dim3 ggrid(DCOLS / BN, NROWS / BM);
    prep_rows<<<NROWS, 256>>>(inc);
    prep_Bscale<<<DCOLS / 8, 256>>>(cur);
    prep_B<<<dim3(NROWS / 32, DCOLS / 32), dim3(32, 8)>>>(cur);
    gemm_term<<<ggrid, 256, SMEM_G>>>(0);    // a1*b1 -> g_part
    gemm_term<<<ggrid, 256, SMEM_G>>>(1);    // a2*b1 -> g_part2
    gemm_final<<<ggrid, 256, SMEM_G>>>((float*)d_out);  // a1*b2 + combine
}

// round 16
// speedup vs baseline: 1.0611x; 1.0111x over previous
#include <cuda_runtime.h>
#include <cuda_bf16.h>
#include <cstdint>

#define NROWS 8192
#define DCOLS 512

// ---------------- scratch (device globals: allocation-free) ----------------
__device__ __align__(256) int8_t g_A1[(size_t)NROWS * NROWS];   // 64 MB
__device__ __align__(256) int8_t g_A2[(size_t)NROWS * NROWS];   // 64 MB
__device__ __align__(256) int8_t g_B1[(size_t)DCOLS * NROWS];   // 4 MB [n][k]
__device__ __align__(256) int8_t g_B2[(size_t)DCOLS * NROWS];   // 4 MB
__device__ __align__(256) int   g_part[(size_t)NROWS * DCOLS];  // 16 MB (a1*b1)
__device__ float g_deg[NROWS];
__device__ float g_Sa[NROWS];
__device__ float g_Sb[DCOLS];

// ---------------- PTX helpers (compute_100-safe: no 'a' features) ----------
__device__ __forceinline__ uint32_t smem_u32(const void* p) {
    uint32_t a;
    asm("{ .reg .u64 t; cvta.to.shared.u64 t, %1; cvt.u32.u64 %0, t; }" : "=r"(a) : "l"(p));
    return a;
}
__device__ __forceinline__ void cp16(uint32_t dst, const void* src) {
    asm volatile("cp.async.cg.shared.global [%0], [%1], 16;" :: "r"(dst), "l"(src));
}
__device__ __forceinline__ void ldsm4(uint32_t* r, uint32_t addr) {
    asm volatile("ldmatrix.sync.aligned.m8n8.x4.shared.b16 {%0,%1,%2,%3}, [%4];"
                 : "=r"(r[0]), "=r"(r[1]), "=r"(r[2]), "=r"(r[3]) : "r"(addr));
}
__device__ __forceinline__ void mma_s8(int* c, const uint32_t* a, const uint32_t* b) {
    asm("mma.sync.aligned.m16n8k32.row.col.s32.s8.s8.s32 "
        "{%0,%1,%2,%3}, {%4,%5,%6,%7}, {%8,%9}, {%0,%1,%2,%3};"
        : "+r"(c[0]), "+r"(c[1]), "+r"(c[2]), "+r"(c[3])
        : "r"(a[0]), "r"(a[1]), "r"(a[2]), "r"(a[3]), "r"(b[0]), "r"(b[1]));
}

// ---------------- P1: row stats + XLA-order deg + int8 quant ----------------
__global__ void __launch_bounds__(256) prep_rows(const float* __restrict__ inc) {
    __shared__ int   red_c[8];
    __shared__ float red_mp[8];
    __shared__ float red_mn[8];
    __shared__ float wpart[32];
    __shared__ float s_hv, s_inv;

    const int r = blockIdx.x;
    const int tid = threadIdx.x;
    const int lane = tid & 31, warp = tid >> 5;
    const float2* src = (const float2*)(inc + (size_t)r * NROWS);

    // load 16 float2 in XLA order: pair p = tid + 256*jv + 1024*i
    float vx[16], vy[16];
    int cnt = 0;
    float mp = 0.f, mn = 0.f;
    #pragma unroll
    for (int jv = 0; jv < 4; jv++) {
        #pragma unroll
        for (int i = 0; i < 4; i++) {
            const int p = tid + 256 * jv + 1024 * i;
            float2 v = src[p];
            vx[jv * 4 + i] = v.x;
            vy[jv * 4 + i] = v.y;
            cnt += (v.x > 0.f) + (v.y > 0.f);
            mp = fmaxf(mp, fmaxf(v.x, v.y));
            mn = fminf(mn, fminf(v.x, v.y));
        }
    }
    for (int o = 16; o; o >>= 1) {
        cnt += __shfl_xor_sync(0xFFFFFFFFu, cnt, o);
        mp = fmaxf(mp, __shfl_xor_sync(0xFFFFFFFFu, mp, o));
        mn = fminf(mn, __shfl_xor_sync(0xFFFFFFFFu, mn, o));
    }
    if (lane == 0) { red_c[warp] = cnt; red_mp[warp] = mp; red_mn[warp] = mn; }
    __syncthreads();
    if (tid == 0) {
        int c = 0;
        float MP = 0.f, MN = 0.f;
        #pragma unroll
        for (int i = 0; i < 8; i++) {
            c += red_c[i];
            MP = fmaxf(MP, red_mp[i]);
            MN = fminf(MN, red_mn[i]);
        }
        float denom = __fsqrt_rn((float)c);
        denom = fmaxf(denom, 1e-12f);
        float hv = __fdiv_rn(1.0f, denom);
        s_hv = hv;
        float m = fmaxf((MP > 0.f) ? (MP + hv) : 0.f, -MN);
        m = fmaxf(m, 1e-30f);
        g_Sa[r] = m / 127.f;
        s_inv = 127.f / m;
    }
    __syncthreads();
    const float hv = s_hv;
    const float inv = s_inv;

    // transform ONCE in registers: a' = (x>0) ? x+hv : x
    #pragma unroll
    for (int e = 0; e < 16; e++) {
        if (vx[e] > 0.f) vx[e] = vx[e] + hv;
        if (vy[e] > 0.f) vy[e] = vy[e] + hv;
    }

    // deg: XLA-GPU row-reduce order mimic
    #pragma unroll
    for (int jv = 0; jv < 4; jv++) {
        float ax = 0.f, ay = 0.f;
        #pragma unroll
        for (int i = 0; i < 4; i++) {
            ax += vx[jv * 4 + i];
            ay += vy[jv * 4 + i];
        }
        float s = ax + ay;
        s += __shfl_down_sync(0xFFFFFFFFu, s, 16);
        s += __shfl_down_sync(0xFFFFFFFFu, s, 8);
        s += __shfl_down_sync(0xFFFFFFFFu, s, 4);
        s += __shfl_down_sync(0xFFFFFFFFu, s, 2);
        s += __shfl_down_sync(0xFFFFFFFFu, s, 1);
        if (lane == 0) wpart[jv * 8 + warp] = s;
    }
    __syncthreads();
    if (tid < 32) {
        float v = wpart[tid];
        v += __shfl_down_sync(0xFFFFFFFFu, v, 16);
        v += __shfl_down_sync(0xFFFFFFFFu, v, 8);
        v += __shfl_down_sync(0xFFFFFFFFu, v, 4);
        v += __shfl_down_sync(0xFFFFFFFFu, v, 2);
        v += __shfl_down_sync(0xFFFFFFFFu, v, 1);
        if (tid == 0) g_deg[r] = v;
    }

    // quantize: a' = Sa*(q1 + q2/254)
    int8_t* A1 = g_A1 + (size_t)r * NROWS;
    int8_t* A2 = g_A2 + (size_t)r * NROWS;
    #pragma unroll
    for (int jv = 0; jv < 4; jv++) {
        #pragma unroll
        for (int i = 0; i < 4; i++) {
            const int j = 2 * tid + 512 * jv + 2048 * i;
            float qx = vx[jv * 4 + i] * inv;
            float qy = vy[jv * 4 + i] * inv;
            int i1x = __float2int_rn(qx);
            int i1y = __float2int_rn(qy);
            int i2x = __float2int_rn(254.f * (qx - (float)i1x));
            int i2y = __float2int_rn(254.f * (qy - (float)i1y));
            *(char2*)(A1 + j) = make_char2((char)i1x, (char)i1y);
            *(char2*)(A2 + j) = make_char2((char)i2x, (char)i2y);
        }
    }
}

// ---------------- P2a: per-column max of cur -> g_Sb ----------------
__global__ void __launch_bounds__(256) prep_Bscale(const float* __restrict__ cur) {
    __shared__ float red[32][8];
    const int tid = threadIdx.x;
    const int nIn = tid & 7;
    const int kp = tid >> 3;
    const int n = blockIdx.x * 8 + nIn;
    float m = 0.f;
    for (int k = kp; k < NROWS; k += 32)
        m = fmaxf(m, fabsf(cur[(size_t)k * DCOLS + n]));
    red[kp][nIn] = m;
    __syncthreads();
    if (tid < 8) {
        float mm = 1e-30f;
        #pragma unroll
        for (int i = 0; i < 32; i++) mm = fmaxf(mm, red[i][tid]);
        g_Sb[blockIdx.x * 8 + tid] = mm / 127.f;
    }
}

// ---------------- P2b: cur [k][n] -> int8 planes [n][k] ----------------
__global__ void __launch_bounds__(256) prep_B(const float* __restrict__ cur) {
    __shared__ float t[32][33];
    const int k0 = blockIdx.x * 32;
    const int n0 = blockIdx.y * 32;
    const int tx = threadIdx.x, ty = threadIdx.y;
    for (int i = ty; i < 32; i += 8)
        t[i][tx] = cur[(size_t)(k0 + i) * DCOLS + n0 + tx];
    __syncthreads();
    for (int i = ty; i < 32; i += 8) {
        const int n = n0 + i;
        float v = t[tx][i];
        float q = v / g_Sb[n];
        int i1 = __float2int_rn(q);
        int i2 = __float2int_rn(254.f * (q - (float)i1));
        size_t o = (size_t)n * NROWS + (size_t)(k0 + tx);
        g_B1[o] = (int8_t)i1;
        g_B2[o] = (int8_t)i2;
    }
}

// ---------------- GEMM: proven BK128 2-plane loop ----------------------------
// CTA tile 128x128, 256 threads, warp grid 4(m) x 2(n), warp tile 32x64.
// grid 4x64 = 256 CTAs, occ 2 -> fully-resident wave per pass.
constexpr int BM = 128, BN = 128;
constexpr int BK = 128, NCH = NROWS / BK;               // 64 chunks
constexpr int TILE = BM * BK;                            // 16 KB per operand
constexpr int STAGE = 2 * TILE;                          // 32 KB
constexpr int SMEM_G = 1024 + 3 * STAGE;                 // 99328

__device__ __forceinline__ void load_stageP(uint32_t st, int c, int m0, int n0, int tid,
                                            const int8_t* Ap, const int8_t* Bp) {
    const size_t rs = (size_t)NROWS;
    const size_t kb = (size_t)c * BK;
    const char* A = (const char*)Ap + (size_t)m0 * rs + kb;
    const char* B = (const char*)Bp + (size_t)n0 * rs + kb;
    #pragma unroll
    for (int i = 0; i < 4; i++) {
        int idx = i * 256 + tid, row = idx >> 3, g = idx & 7;
        cp16(st + row * 128 + ((g ^ (row & 7)) << 4), A + (size_t)row * rs + (size_t)g * 16);
    }
    const uint32_t bs = st + TILE;
    #pragma unroll
    for (int i = 0; i < 4; i++) {
        int idx = i * 256 + tid, row = idx >> 3, g = idx & 7;
        cp16(bs + row * 128 + ((g ^ (row & 7)) << 4), B + (size_t)row * rs + (size_t)g * 16);
    }
}

// Shared mainloop: accumulates Ap x Bp^T tile into am (exact int32).
__device__ __forceinline__ void gemm_loop(int am[2][8][4], const int8_t* Ap,
                                          const int8_t* Bp, uint32_t stage0,
                                          int m0, int n0, int tid,
                                          const int* aRow, const int* bRow,
                                          int aSel, int bSel) {
    #pragma unroll
    for (int s = 0; s < 2; s++) {
        load_stageP(stage0 + s * STAGE, s, m0, n0, tid, Ap, Bp);
        asm volatile("cp.async.commit_group;" ::: "memory");
    }
    for (int c = 0; c < NCH; c++) {
        asm volatile("cp.async.wait_group 1;" ::: "memory");
        __syncthreads();
        if (c + 2 < NCH) load_stageP(stage0 + ((c + 2) % 3) * STAGE, c + 2, m0, n0, tid, Ap, Bp);
        asm volatile("cp.async.commit_group;" ::: "memory");

        const uint32_t st = stage0 + (c % 3) * STAGE;
        const uint32_t aB = st, bB = st + TILE;
        #pragma unroll
        for (int s = 0; s < 4; s++) {        // four k32 steps
            uint32_t ah[8], bb[8];
            #pragma unroll
            for (int mi = 0; mi < 2; mi++)
                ldsm4(&ah[4 * mi], aB + aRow[mi] * 128 +
                      (((2 * s + aSel) ^ (aRow[mi] & 7)) << 4));
            #pragma unroll
            for (int h = 0; h < 2; h++) {
                #pragma unroll
                for (int g = 0; g < 2; g++) {
                    const int f = 2 * h + g;
                    ldsm4(&bb[4 * g], bB + bRow[f] * 128 +
                          (((2 * s + bSel) ^ (bRow[f] & 7)) << 4));
                }
                #pragma unroll
                for (int mi = 0; mi < 2; mi++)
                    #pragma unroll
                    for (int j = 0; j < 4; j++)
                        mma_s8(am[mi][4 * h + j], &ah[4 * mi], &bb[2 * j]);
            }
        }
    }
}

// pass 1: A1*B1 -> g_part (int32 partials)
__global__ void __launch_bounds__(256, 2) gemm_term(void) {
    extern __shared__ char smem_raw[];
    const uint32_t sb = (smem_u32(smem_raw) + 1023u) & ~1023u;
    const int tid = threadIdx.x, lane = tid & 31, w = tid >> 5;
    const int wm = w & 3, wn = w >> 2;
    const int m0 = blockIdx.y * BM, n0 = blockIdx.x * BN;

    int aRow[2], bRow[4];
    #pragma unroll
    for (int mi = 0; mi < 2; mi++) aRow[mi] = wm * 32 + mi * 16 + (lane & 15);
    #pragma unroll
    for (int f = 0; f < 4; f++)
        bRow[f] = wn * 64 + f * 16 + ((lane >> 4) << 3) + (lane & 7);
    const int aSel = lane >> 4;
    const int bSel = (lane >> 3) & 1;

    int am[2][8][4] = {};
    gemm_loop(am, g_A1, g_B1, sb + 1024, m0, n0, tid, aRow, bRow, aSel, bSel);

    const int cw = n0 + wn * 64 + (lane & 3) * 2;
    #pragma unroll
    for (int mi = 0; mi < 2; mi++) {
        const int r0 = m0 + wm * 32 + mi * 16 + (lane >> 2);
        int* p0 = g_part + (size_t)r0 * DCOLS;
        int* p1 = g_part + (size_t)(r0 + 8) * DCOLS;
        #pragma unroll
        for (int ni = 0; ni < 8; ni++) {
            *(int2*)(p0 + cw + ni * 8) = make_int2(am[mi][ni][0], am[mi][ni][1]);
            *(int2*)(p1 + cw + ni * 8) = make_int2(am[mi][ni][2], am[mi][ni][3]);
        }
    }
}

// pass 2: ax = A2*B1 + A1*B2 (two sequential proven loops, shared exact int acc);
// epilogue: fea = Sa*Sb*(part + ax/254); out = fea/deg (RN)
__global__ void __launch_bounds__(256, 2) gemm_final(float* __restrict__ out) {
    extern __shared__ char smem_raw[];
    const uint32_t sb = (smem_u32(smem_raw) + 1023u) & ~1023u;
    const int tid = threadIdx.x, lane = tid & 31, w = tid >> 5;
    const int wm = w & 3, wn = w >> 2;
    const int m0 = blockIdx.y * BM, n0 = blockIdx.x * BN;

    int aRow[2], bRow[4];
    #pragma unroll
    for (int mi = 0; mi < 2; mi++) aRow[mi] = wm * 32 + mi * 16 + (lane & 15);
    #pragma unroll
    for (int f = 0; f < 4; f++)
        bRow[f] = wn * 64 + f * 16 + ((lane >> 4) << 3) + (lane & 7);
    const int aSel = lane >> 4;
    const int bSel = (lane >> 3) & 1;

    int ax[2][8][4] = {};
    gemm_loop(ax, g_A2, g_B1, sb + 1024, m0, n0, tid, aRow, bRow, aSel, bSel);
    // all warps finished reading phase-1 stage buffers before phase-2 overwrites
    __syncthreads();
    gemm_loop(ax, g_A1, g_B2, sb + 1024, m0, n0, tid, aRow, bRow, aSel, bSel);

    const float C = 1.f / 254.f;
    const int cw = n0 + wn * 64 + (lane & 3) * 2;
    #pragma unroll
    for (int mi = 0; mi < 2; mi++) {
        const int r0 = m0 + wm * 32 + mi * 16 + (lane >> 2);
        const float d0 = g_deg[r0], d1 = g_deg[r0 + 8];
        const float sa0 = g_Sa[r0], sa1 = g_Sa[r0 + 8];
        const int* q0 = g_part + (size_t)r0 * DCOLS;
        const int* q1 = g_part + (size_t)(r0 + 8) * DCOLS;
        float* p0 = out + (size_t)r0 * DCOLS;
        float* p1 = out + (size_t)(r0 + 8) * DCOLS;
        #pragma unroll
        for (int ni = 0; ni < 8; ni++) {
            const int col = cw + ni * 8;
            float2 sbv = *(const float2*)(g_Sb + col);
            int2 m0v = *(const int2*)(q0 + col);
            int2 m1v = *(const int2*)(q1 + col);
            float f00 = sa0 * sbv.x * ((float)m0v.x + (float)ax[mi][ni][0] * C);
            float f01 = sa0 * sbv.y * ((float)m0v.y + (float)ax[mi][ni][1] * C);
            float f10 = sa1 * sbv.x * ((float)m1v.x + (float)ax[mi][ni][2] * C);
            float f11 = sa1 * sbv.y * ((float)m1v.y + (float)ax[mi][ni][3] * C);
            *(float2*)(p0 + col) = make_float2(__fdiv_rn(f00, d0), __fdiv_rn(f01, d0));
            *(float2*)(p1 + col) = make_float2(__fdiv_rn(f10, d1), __fdiv_rn(f11, d1));
        }
    }
}

// ---------------- launch ----------------
extern "C" void kernel_launch(void* const* d_in, const int* in_sizes, int n_in,
                              void* d_out, int out_size) {
    const float* cur = (const float*)d_in[0];
    const float* inc = (const float*)d_in[1];
    if (n_in >= 2 && in_sizes[0] == NROWS * NROWS) {  // defensive input-order check
        inc = (const float*)d_in[0];
        cur = (const float*)d_in[1];
    }
    cudaFuncSetAttribute(gemm_term, cudaFuncAttributeMaxDynamicSharedMemorySize, SMEM_G);
    cudaFuncSetAttribute(gemm_final, cudaFuncAttributeMaxDynamicSharedMemorySize, SMEM_G);

    dim3 ggrid(DCOLS / BN, NROWS / BM);
    prep_rows<<<NROWS, 256>>>(inc);
    prep_Bscale<<<DCOLS / 8, 256>>>(cur);
    prep_B<<<dim3(NROWS / 32, DCOLS / 32), dim3(32, 8)>>>(cur);
    gemm_term<<<ggrid, 256, SMEM_G>>>();                 // a1*b1 -> g_part
    gemm_final<<<ggrid, 256, SMEM_G>>>((float*)d_out);   // a2*b1 + a1*b2 + combine
}